// round 7
// baseline (speedup 1.0000x reference)
#include <cuda_runtime.h>
#include <cuda_bf16.h>
#include <mma.h>
#include <cstdint>

using namespace nvcuda;

#define N_AG 4096
#define M_CL 256
#define KD 32
#define NF 561
#define PF 576             /* g_P row stride */
#define CATK 12288         /* 3 * 4096 concatenated K */
#define CATF 640           /* padded feature rows (5 * 128) */
#define KSPLIT 16
#define KCH (CATK / KSPLIT)   /* 768 */
#define TGK 64             /* K per smem chunk */
#define SLD 72             /* smem leading dim (bf16 elems), 144B rows */
#define CNT_BLKS 128
#define W_EPS 1e-6f

// static scratch (no allocations allowed)
__device__ float g_P[(size_t)N_AG * PF];
__device__ __align__(256) __nv_bfloat16 g_Acat[(size_t)M_CL * CATK];
__device__ __align__(256) __nv_bfloat16 g_Bcat[(size_t)CATF * CATK];
__device__ float g_part[(size_t)KSPLIT * M_CL * CATF];
__device__ float g_S[(size_t)M_CL * CATF];
__device__ float g_gtri[(size_t)M_CL * 528];
__device__ float g_cnt[CNT_BLKS * M_CL];

// ---------------------------------------------------------------------------
// Kernel A: batched 32x32 SPD solve fused with feature build (unchanged).
// ---------------------------------------------------------------------------
__global__ void __launch_bounds__(256) solve_feat_kernel(const float* __restrict__ A,
                                                         const float* __restrict__ rhs) {
  __shared__ __align__(16) float prow[8][36];
  int t = threadIdx.x, wid = t >> 5, lane = t & 31;
  int n = blockIdx.x * 8 + wid;
  const float* Ar = A + (size_t)n * (KD * KD) + lane * KD;

  float a[KD];
#pragma unroll
  for (int q = 0; q < 8; q++) {
    float4 v4 = *reinterpret_cast<const float4*>(Ar + 4 * q);
    a[4 * q + 0] = v4.x; a[4 * q + 1] = v4.y;
    a[4 * q + 2] = v4.z; a[4 * q + 3] = v4.w;
  }
  float b = rhs[n * KD + lane];
  float diag = 1.0f;
  float* pr = prow[wid];

#pragma unroll
  for (int j = 0; j < KD; j++) {
    if (lane == j) {
#pragma unroll
      for (int q = 0; q < 8; q++)
        if (4 * q + 3 >= j)
          *reinterpret_cast<float4*>(&pr[4 * q]) =
              make_float4(a[4 * q], a[4 * q + 1], a[4 * q + 2], a[4 * q + 3]);
      pr[32] = b;
      diag = a[j];
    }
    __syncwarp();
    float pd  = pr[j];
    float bp  = pr[32];
    float inv = 1.0f / pd;
    float f   = (lane == j) ? 0.0f : a[j] * inv;
#pragma unroll
    for (int q = 0; q < 8; q++)
      if (4 * q + 3 >= j) {
        float4 pv = *reinterpret_cast<const float4*>(&pr[4 * q]);
        a[4 * q + 0] = fmaf(-f, pv.x, a[4 * q + 0]);
        a[4 * q + 1] = fmaf(-f, pv.y, a[4 * q + 1]);
        a[4 * q + 2] = fmaf(-f, pv.z, a[4 * q + 2]);
        a[4 * q + 3] = fmaf(-f, pv.w, a[4 * q + 3]);
      }
    b = fmaf(-f, bp, b);
    __syncwarp();
  }
  float x = b / diag;

  pr[lane] = x;
  __syncwarp();
  float xv[KD];
#pragma unroll
  for (int q = 0; q < 8; q++) {
    float4 v4 = *reinterpret_cast<const float4*>(&pr[4 * q]);
    xv[4 * q + 0] = v4.x; xv[4 * q + 1] = v4.y;
    xv[4 * q + 2] = v4.z; xv[4 * q + 3] = v4.w;
  }
  float* Pn = g_P + (size_t)n * PF;
  Pn[lane] = x;
  int base = KD;
#pragma unroll
  for (int k = 0; k < KD; k++) {
    if (lane >= k) Pn[base + lane - k] = xv[k] * x;
    base += KD - k;
  }
  if (lane == 0) Pn[560] = 1.0f;
  if (lane < 15) Pn[561 + lane] = 0.0f;
}

// ---------------------------------------------------------------------------
// prepA: transpose + mask W(n,m) -> A_cat[m][k] bf16, segments [hi | hi | lo].
// ---------------------------------------------------------------------------
__global__ void __launch_bounds__(256) prepA_kernel(const float* __restrict__ W) {
  __shared__ float tile[32][33];
  int n0 = blockIdx.x * 32, m0 = blockIdx.y * 32;
  int r = threadIdx.x >> 5, c = threadIdx.x & 31;
#pragma unroll
  for (int i = 0; i < 4; i++) {
    int rr = r + i * 8;
    float w = W[(size_t)(n0 + rr) * M_CL + m0 + c];
    tile[rr][c] = (w >= W_EPS) ? w : 0.0f;
  }
  __syncthreads();
#pragma unroll
  for (int i = 0; i < 4; i++) {
    int rr = r + i * 8;                       // m offset
    float val = tile[c][rr];                  // [n=c][m=rr]
    __nv_bfloat16 hi = __float2bfloat16(val);
    __nv_bfloat16 lo = __float2bfloat16(val - __bfloat162float(hi));
    size_t row = (size_t)(m0 + rr) * CATK;
    g_Acat[row + n0 + c]        = hi;
    g_Acat[row + 4096 + n0 + c] = hi;
    g_Acat[row + 8192 + n0 + c] = lo;
  }
}

// ---------------------------------------------------------------------------
// prepB: transpose g_P(n,f) -> B_cat[f][k] bf16, segments [hi | lo | hi].
// ---------------------------------------------------------------------------
__global__ void __launch_bounds__(256) prepB_kernel() {
  __shared__ float tile[32][33];
  int n0 = blockIdx.x * 32, f0 = blockIdx.y * 32;
  int r = threadIdx.x >> 5, c = threadIdx.x & 31;
#pragma unroll
  for (int i = 0; i < 4; i++) {
    int rr = r + i * 8;
    float p = (f0 + c < PF) ? g_P[(size_t)(n0 + rr) * PF + f0 + c] : 0.0f;
    tile[rr][c] = p;
  }
  __syncthreads();
#pragma unroll
  for (int i = 0; i < 4; i++) {
    int rr = r + i * 8;                       // f offset
    float val = tile[c][rr];
    __nv_bfloat16 hi = __float2bfloat16(val);
    __nv_bfloat16 lo = __float2bfloat16(val - __bfloat162float(hi));
    size_t row = (size_t)(f0 + rr) * CATK;
    g_Bcat[row + n0 + c]        = hi;
    g_Bcat[row + 4096 + n0 + c] = lo;
    g_Bcat[row + 8192 + n0 + c] = hi;
  }
}

// ---------------------------------------------------------------------------
// gsq: per-m packed triangle of G = Omega^2 with symmetry multiplier.
// ---------------------------------------------------------------------------
__global__ void __launch_bounds__(256) gsq_kernel(const float* __restrict__ Omega) {
  __shared__ float sO[KD * KD];
  int m = blockIdx.x, t = threadIdx.x;
  for (int e = t; e < KD * KD; e += 256) sO[e] = Omega[(size_t)m * KD * KD + e];
  __syncthreads();
  for (int ft = t; ft < 528; ft += 256) {
    float disc = 4225.0f - 8.0f * (float)ft;
    int k = (int)((65.0f - sqrtf(disc)) * 0.5f);
    int b0 = k * KD - (k * (k - 1)) / 2;
    if (ft < b0) { k--; b0 = k * KD - (k * (k - 1)) / 2; }
    else if (ft >= b0 + (KD - k)) { k++; b0 = k * KD - (k * (k - 1)) / 2; }
    int l = k + (ft - b0);
    float g = 0.0f;
#pragma unroll
    for (int q = 0; q < KD; q++) g = fmaf(sO[k * KD + q], sO[l * KD + q], g);
    g_gtri[(size_t)m * 528 + ft] = (k == l) ? g : 2.0f * g;
  }
}

// ---------------------------------------------------------------------------
// cnt: mask count per m.
// ---------------------------------------------------------------------------
__global__ void __launch_bounds__(256) cnt_kernel(const float* __restrict__ W) {
  int m = threadIdx.x;
  int nb = blockIdx.x * 32;
  float c = 0.0f;
#pragma unroll 8
  for (int r = 0; r < 32; r++)
    c += (W[(size_t)(nb + r) * M_CL + m] >= W_EPS) ? 1.0f : 0.0f;
  g_cnt[blockIdx.x * M_CL + m] = c;
}

// ---------------------------------------------------------------------------
// tgemm: wmma bf16 tensor-core GEMM.  D[128m,128f] tile per CTA, K-split 16.
// 8 warps in 2(m) x 4(f) grid; warp tile 64m x 32f = 4x2 wmma 16x16x16 frags.
// Single smem buffer + register prefetch of the next chunk.
// ---------------------------------------------------------------------------
__global__ void __launch_bounds__(256) tgemm_kernel() {
  __shared__ __align__(16) __nv_bfloat16 sA[128 * SLD];
  __shared__ __align__(16) __nv_bfloat16 sB[128 * SLD];

  int t = threadIdx.x, wid = t >> 5;
  int m0 = blockIdx.x * 128;
  int f0 = blockIdx.y * 128;
  int kbase = blockIdx.z * KCH;

  int wm = wid >> 2, wf = wid & 3;    // warp tile origin: (wm*64, wf*32)

  wmma::fragment<wmma::accumulator, 16, 16, 16, float> acc[4][2];
#pragma unroll
  for (int i = 0; i < 4; i++)
#pragma unroll
    for (int j = 0; j < 2; j++) wmma::fill_fragment(acc[i][j], 0.0f);

  // loader coords: 128 rows x 64 cols bf16 = 8 x uint4 per row
  int lrow = t >> 1, lc = (t & 1) * 4;   // each thread: 4 uint4 in one row half

  uint4 pa[4], pb[4];
#pragma unroll
  for (int u = 0; u < 4; u++) {
    pa[u] = *reinterpret_cast<const uint4*>(
        &g_Acat[(size_t)(m0 + lrow) * CATK + kbase + (lc + u) * 8]);
    pb[u] = *reinterpret_cast<const uint4*>(
        &g_Bcat[(size_t)(f0 + lrow) * CATK + kbase + (lc + u) * 8]);
  }

  const int NCH = KCH / TGK;           // 12
  for (int ch = 0; ch < NCH; ch++) {
    __syncthreads();
#pragma unroll
    for (int u = 0; u < 4; u++) {
      *reinterpret_cast<uint4*>(&sA[lrow * SLD + (lc + u) * 8]) = pa[u];
      *reinterpret_cast<uint4*>(&sB[lrow * SLD + (lc + u) * 8]) = pb[u];
    }
    __syncthreads();
    if (ch + 1 < NCH) {
      int kc = kbase + (ch + 1) * TGK;
#pragma unroll
      for (int u = 0; u < 4; u++) {
        pa[u] = *reinterpret_cast<const uint4*>(
            &g_Acat[(size_t)(m0 + lrow) * CATK + kc + (lc + u) * 8]);
        pb[u] = *reinterpret_cast<const uint4*>(
            &g_Bcat[(size_t)(f0 + lrow) * CATK + kc + (lc + u) * 8]);
      }
    }
#pragma unroll
    for (int kk = 0; kk < TGK / 16; kk++) {
      wmma::fragment<wmma::matrix_a, 16, 16, 16, __nv_bfloat16, wmma::row_major> af[4];
      wmma::fragment<wmma::matrix_b, 16, 16, 16, __nv_bfloat16, wmma::col_major> bf[2];
#pragma unroll
      for (int i = 0; i < 4; i++)
        wmma::load_matrix_sync(af[i], &sA[(wm * 64 + i * 16) * SLD + kk * 16], SLD);
#pragma unroll
      for (int j = 0; j < 2; j++)
        wmma::load_matrix_sync(bf[j], &sB[(wf * 32 + j * 16) * SLD + kk * 16], SLD);
#pragma unroll
      for (int i = 0; i < 4; i++)
#pragma unroll
        for (int j = 0; j < 2; j++)
          wmma::mma_sync(acc[i][j], af[i], bf[j], acc[i][j]);
    }
  }

  float* pbase = g_part + (size_t)blockIdx.z * M_CL * CATF;
#pragma unroll
  for (int i = 0; i < 4; i++)
#pragma unroll
    for (int j = 0; j < 2; j++)
      wmma::store_matrix_sync(
          &pbase[(size_t)(m0 + wm * 64 + i * 16) * CATF + f0 + wf * 32 + j * 16],
          acc[i][j], CATF, wmma::mem_row_major);
}

// ---------------------------------------------------------------------------
// reduce: g_part[16][256][640] -> g_S[256][640], one thread per element.
// ---------------------------------------------------------------------------
__global__ void __launch_bounds__(256) reduce_kernel() {
  int idx = blockIdx.x * 256 + threadIdx.x;
  float a = 0.0f;
#pragma unroll
  for (int ks = 0; ks < KSPLIT; ks++)
    a += g_part[(size_t)ks * M_CL * CATF + idx];
  g_S[idx] = a;
}

// ---------------------------------------------------------------------------
// final: one warp per m.
// ---------------------------------------------------------------------------
__global__ void __launch_bounds__(256) final_kernel(const float* __restrict__ Omega,
                                                    float* __restrict__ out) {
  int t = threadIdx.x, wid = t >> 5, lane = t & 31;
  int m = blockIdx.x * 8 + wid;

  const float* Sm = g_S + (size_t)m * CATF;
  const float* Gm = g_gtri + (size_t)m * 528;

  float s_l = Sm[lane];
  float Z   = Sm[560];

  float tr = 0.0f;
#pragma unroll
  for (int i = 0; i < 17; i++) {
    int ft = lane + i * 32;
    if (ft < 528) tr = fmaf(Gm[ft], Sm[32 + ft], tr);
  }

  const float* Om = Omega + (size_t)m * KD * KD + lane * KD;
  float u = 0.0f;
#pragma unroll
  for (int q4 = 0; q4 < 8; q4++) {
    float4 o4 = *reinterpret_cast<const float4*>(Om + 4 * q4);
    u = fmaf(o4.x, __shfl_sync(0xffffffffu, s_l, 4 * q4 + 0), u);
    u = fmaf(o4.y, __shfl_sync(0xffffffffu, s_l, 4 * q4 + 1), u);
    u = fmaf(o4.z, __shfl_sync(0xffffffffu, s_l, 4 * q4 + 2), u);
    u = fmaf(o4.w, __shfl_sync(0xffffffffu, s_l, 4 * q4 + 3), u);
  }
  float usq = u * u;

  float c = 0.0f;
#pragma unroll
  for (int i = 0; i < CNT_BLKS / 32; i++)
    c += g_cnt[(lane * (CNT_BLKS / 32) + i) * M_CL + m];

#pragma unroll
  for (int s = 16; s > 0; s >>= 1) {
    tr  += __shfl_down_sync(0xffffffffu, tr, s);
    usq += __shfl_down_sync(0xffffffffu, usq, s);
    c   += __shfl_down_sync(0xffffffffu, c, s);
  }
  if (lane == 0) {
    float Zs  = fmaxf(Z, 1e-30f);
    float psi = tr / Zs - usq / (Zs * Zs);
    out[m] = (c >= 1.5f) ? psi : 0.0f;
  }
}

// ---------------------------------------------------------------------------
extern "C" void kernel_launch(void* const* d_in, const int* in_sizes, int n_in,
                              void* d_out, int out_size) {
  const float* W            = (const float*)d_in[0];  // (N, M)
  const float* mu_s         = (const float*)d_in[1];  // (N, K)
  const float* omega_child  = (const float*)d_in[2];  // (N, K, K)
  const float* omega_parent = (const float*)d_in[3];  // (M, K, K)
  float* out = (float*)d_out;                         // (M,)

  gsq_kernel<<<M_CL, 256>>>(omega_parent);
  solve_feat_kernel<<<N_AG / 8, 256>>>(omega_child, mu_s);
  prepA_kernel<<<dim3(N_AG / 32, M_CL / 32), 256>>>(W);
  cnt_kernel<<<CNT_BLKS, 256>>>(W);
  prepB_kernel<<<dim3(N_AG / 32, CATF / 32), 256>>>();
  tgemm_kernel<<<dim3(2, 5, KSPLIT), 256>>>();
  reduce_kernel<<<(M_CL * CATF) / 256, 256>>>();
  final_kernel<<<M_CL / 8, 256>>>(omega_parent, out);
}

// round 8
// speedup vs baseline: 1.1142x; 1.1142x over previous
#include <cuda_runtime.h>
#include <cuda_bf16.h>
#include <mma.h>
#include <cstdint>

using namespace nvcuda;

#define N_AG 4096
#define M_CL 256
#define KD 32
#define NF 561
#define PF 640             /* g_P row stride == padded feature count (5*128) */
#define KSPLIT 16
#define NCHUNK 8           /* 256 n per split / 32 per chunk */
#define TGCH 32            /* n per smem chunk */
#define ALD 136            /* smem leading dim (bf16 elems) */
#define CNT_BLKS 128
#define W_EPS 1e-6f

// static scratch (no allocations allowed)
__device__ float g_P[(size_t)N_AG * PF];
__device__ float g_part[(size_t)KSPLIT * M_CL * PF];
__device__ float g_S[(size_t)M_CL * PF];
__device__ float g_gtri[(size_t)M_CL * 528];
__device__ float g_cnt[CNT_BLKS * M_CL];

// ---------------------------------------------------------------------------
// Kernel A: batched 32x32 SPD solve fused with feature build.
// ---------------------------------------------------------------------------
__global__ void __launch_bounds__(256) solve_feat_kernel(const float* __restrict__ A,
                                                         const float* __restrict__ rhs) {
  __shared__ __align__(16) float prow[8][36];
  int t = threadIdx.x, wid = t >> 5, lane = t & 31;
  int n = blockIdx.x * 8 + wid;
  const float* Ar = A + (size_t)n * (KD * KD) + lane * KD;

  float a[KD];
#pragma unroll
  for (int q = 0; q < 8; q++) {
    float4 v4 = *reinterpret_cast<const float4*>(Ar + 4 * q);
    a[4 * q + 0] = v4.x; a[4 * q + 1] = v4.y;
    a[4 * q + 2] = v4.z; a[4 * q + 3] = v4.w;
  }
  float b = rhs[n * KD + lane];
  float diag = 1.0f;
  float* pr = prow[wid];

#pragma unroll
  for (int j = 0; j < KD; j++) {
    if (lane == j) {
#pragma unroll
      for (int q = 0; q < 8; q++)
        if (4 * q + 3 >= j)
          *reinterpret_cast<float4*>(&pr[4 * q]) =
              make_float4(a[4 * q], a[4 * q + 1], a[4 * q + 2], a[4 * q + 3]);
      pr[32] = b;
      diag = a[j];
    }
    __syncwarp();
    float pd  = pr[j];
    float bp  = pr[32];
    float inv = 1.0f / pd;
    float f   = (lane == j) ? 0.0f : a[j] * inv;
#pragma unroll
    for (int q = 0; q < 8; q++)
      if (4 * q + 3 >= j) {
        float4 pv = *reinterpret_cast<const float4*>(&pr[4 * q]);
        a[4 * q + 0] = fmaf(-f, pv.x, a[4 * q + 0]);
        a[4 * q + 1] = fmaf(-f, pv.y, a[4 * q + 1]);
        a[4 * q + 2] = fmaf(-f, pv.z, a[4 * q + 2]);
        a[4 * q + 3] = fmaf(-f, pv.w, a[4 * q + 3]);
      }
    b = fmaf(-f, bp, b);
    __syncwarp();
  }
  float x = b / diag;

  pr[lane] = x;
  __syncwarp();
  float xv[KD];
#pragma unroll
  for (int q = 0; q < 8; q++) {
    float4 v4 = *reinterpret_cast<const float4*>(&pr[4 * q]);
    xv[4 * q + 0] = v4.x; xv[4 * q + 1] = v4.y;
    xv[4 * q + 2] = v4.z; xv[4 * q + 3] = v4.w;
  }
  float* Pn = g_P + (size_t)n * PF;
  Pn[lane] = x;
  int base = KD;
#pragma unroll
  for (int k = 0; k < KD; k++) {
    if (lane >= k) Pn[base + lane - k] = xv[k] * x;
    base += KD - k;
  }
  if (lane == 0) Pn[560] = 1.0f;
  for (int f = 561 + lane; f < PF; f += 32) Pn[f] = 0.0f;   // zero pad 561..639
}

// ---------------------------------------------------------------------------
// gsq: per-m packed triangle of G = Omega^2 with symmetry multiplier.
// ---------------------------------------------------------------------------
__global__ void __launch_bounds__(256) gsq_kernel(const float* __restrict__ Omega) {
  __shared__ float sO[KD * KD];
  int m = blockIdx.x, t = threadIdx.x;
  for (int e = t; e < KD * KD; e += 256) sO[e] = Omega[(size_t)m * KD * KD + e];
  __syncthreads();
  for (int ft = t; ft < 528; ft += 256) {
    float disc = 4225.0f - 8.0f * (float)ft;
    int k = (int)((65.0f - sqrtf(disc)) * 0.5f);
    int b0 = k * KD - (k * (k - 1)) / 2;
    if (ft < b0) { k--; b0 = k * KD - (k * (k - 1)) / 2; }
    else if (ft >= b0 + (KD - k)) { k++; b0 = k * KD - (k * (k - 1)) / 2; }
    int l = k + (ft - b0);
    float g = 0.0f;
#pragma unroll
    for (int q = 0; q < KD; q++) g = fmaf(sO[k * KD + q], sO[l * KD + q], g);
    g_gtri[(size_t)m * 528 + ft] = (k == l) ? g : 2.0f * g;
  }
}

// ---------------------------------------------------------------------------
// cnt: float4-coalesced mask count. Block = 32 n-rows; thread group rg (4)
// covers 8 rows each for its 4-m quad; shared reduce across groups.
// ---------------------------------------------------------------------------
__global__ void __launch_bounds__(256) cnt_kernel(const float* __restrict__ W) {
  __shared__ float sc[4][256];
  int t = threadIdx.x;
  int rg = t >> 6, m4 = (t & 63) * 4;
  int nb = blockIdx.x * 32 + rg * 8;
  float4 c = make_float4(0.f, 0.f, 0.f, 0.f);
#pragma unroll
  for (int i = 0; i < 8; i++) {
    float4 w = *reinterpret_cast<const float4*>(&W[(size_t)(nb + i) * M_CL + m4]);
    c.x += (w.x >= W_EPS) ? 1.0f : 0.0f;
    c.y += (w.y >= W_EPS) ? 1.0f : 0.0f;
    c.z += (w.z >= W_EPS) ? 1.0f : 0.0f;
    c.w += (w.w >= W_EPS) ? 1.0f : 0.0f;
  }
  *reinterpret_cast<float4*>(&sc[rg][m4]) = c;
  __syncthreads();
  if (t < 64) {
    int m = t * 4;
    float4 a0 = *reinterpret_cast<float4*>(&sc[0][m]);
    float4 a1 = *reinterpret_cast<float4*>(&sc[1][m]);
    float4 a2 = *reinterpret_cast<float4*>(&sc[2][m]);
    float4 a3 = *reinterpret_cast<float4*>(&sc[3][m]);
    float4 o = make_float4(a0.x + a1.x + a2.x + a3.x, a0.y + a1.y + a2.y + a3.y,
                           a0.z + a1.z + a2.z + a3.z, a0.w + a1.w + a2.w + a3.w);
    *reinterpret_cast<float4*>(&g_cnt[blockIdx.x * M_CL + m]) = o;
  }
}

// ---------------------------------------------------------------------------
// tgemm: wmma bf16 with IN-KERNEL hi/lo split, no transposes, no prep pass.
//   A = masked W  (smem [k][m], native W layout -> matrix_a col_major)
//   B = g_P       (smem [k][f], native P layout -> matrix_b row_major)
// Per 32-n chunk: coalesced fp32 loads -> hi/lo bf16 smem tiles -> 3 mma
// passes (hi*hi + hi*lo + lo*hi).  D tile 128m x 128f, K-split 16.
// ---------------------------------------------------------------------------
__global__ void __launch_bounds__(256) tgemm_kernel(const float* __restrict__ W) {
  __shared__ __align__(16) __nv_bfloat16 sAhi[TGCH * ALD];
  __shared__ __align__(16) __nv_bfloat16 sAlo[TGCH * ALD];
  __shared__ __align__(16) __nv_bfloat16 sBhi[TGCH * ALD];
  __shared__ __align__(16) __nv_bfloat16 sBlo[TGCH * ALD];

  int t = threadIdx.x, wid = t >> 5;
  int m0 = blockIdx.x * 128;
  int f0 = blockIdx.y * 128;
  int nb = blockIdx.z * (N_AG / KSPLIT);   // 256-n split
  int row = t >> 3;                        // 0..31  (n within chunk)
  int c8  = t & 7;                         // float4 slot

  int wm = wid >> 2, wf = wid & 3;         // warp tile: 64m x 32f

  wmma::fragment<wmma::accumulator, 16, 16, 16, float> acc[4][2];
#pragma unroll
  for (int i = 0; i < 4; i++)
#pragma unroll
    for (int j = 0; j < 2; j++) wmma::fill_fragment(acc[i][j], 0.0f);

  float4 pa[4], pb[4];
#pragma unroll
  for (int u = 0; u < 4; u++) {
    pa[u] = *reinterpret_cast<const float4*>(
        &W[(size_t)(nb + row) * M_CL + m0 + (c8 + u * 8) * 4]);
    pb[u] = *reinterpret_cast<const float4*>(
        &g_P[(size_t)(nb + row) * PF + f0 + (c8 + u * 8) * 4]);
  }

  for (int ch = 0; ch < NCHUNK; ch++) {
    __syncthreads();
#pragma unroll
    for (int u = 0; u < 4; u++) {
      float4 w = pa[u];
      w.x = (w.x >= W_EPS) ? w.x : 0.0f;
      w.y = (w.y >= W_EPS) ? w.y : 0.0f;
      w.z = (w.z >= W_EPS) ? w.z : 0.0f;
      w.w = (w.w >= W_EPS) ? w.w : 0.0f;
      __nv_bfloat16 hx = __float2bfloat16(w.x), hy = __float2bfloat16(w.y);
      __nv_bfloat16 hz = __float2bfloat16(w.z), hw = __float2bfloat16(w.w);
      __nv_bfloat162 h01, h23, l01, l23;
      h01.x = hx; h01.y = hy; h23.x = hz; h23.y = hw;
      l01.x = __float2bfloat16(w.x - __bfloat162float(hx));
      l01.y = __float2bfloat16(w.y - __bfloat162float(hy));
      l23.x = __float2bfloat16(w.z - __bfloat162float(hz));
      l23.y = __float2bfloat16(w.w - __bfloat162float(hw));
      int off = row * ALD + (c8 + u * 8) * 4;
      *reinterpret_cast<__nv_bfloat162*>(&sAhi[off])     = h01;
      *reinterpret_cast<__nv_bfloat162*>(&sAhi[off + 2]) = h23;
      *reinterpret_cast<__nv_bfloat162*>(&sAlo[off])     = l01;
      *reinterpret_cast<__nv_bfloat162*>(&sAlo[off + 2]) = l23;

      float4 p = pb[u];
      __nv_bfloat16 px = __float2bfloat16(p.x), py = __float2bfloat16(p.y);
      __nv_bfloat16 pz = __float2bfloat16(p.z), pw = __float2bfloat16(p.w);
      __nv_bfloat162 q01, q23, r01, r23;
      q01.x = px; q01.y = py; q23.x = pz; q23.y = pw;
      r01.x = __float2bfloat16(p.x - __bfloat162float(px));
      r01.y = __float2bfloat16(p.y - __bfloat162float(py));
      r23.x = __float2bfloat16(p.z - __bfloat162float(pz));
      r23.y = __float2bfloat16(p.w - __bfloat162float(pw));
      *reinterpret_cast<__nv_bfloat162*>(&sBhi[off])     = q01;
      *reinterpret_cast<__nv_bfloat162*>(&sBhi[off + 2]) = q23;
      *reinterpret_cast<__nv_bfloat162*>(&sBlo[off])     = r01;
      *reinterpret_cast<__nv_bfloat162*>(&sBlo[off + 2]) = r23;
    }
    __syncthreads();
    if (ch + 1 < NCHUNK) {
      int n1 = nb + (ch + 1) * TGCH;
#pragma unroll
      for (int u = 0; u < 4; u++) {
        pa[u] = *reinterpret_cast<const float4*>(
            &W[(size_t)(n1 + row) * M_CL + m0 + (c8 + u * 8) * 4]);
        pb[u] = *reinterpret_cast<const float4*>(
            &g_P[(size_t)(n1 + row) * PF + f0 + (c8 + u * 8) * 4]);
      }
    }
#pragma unroll
    for (int kk = 0; kk < 2; kk++) {
      wmma::fragment<wmma::matrix_a, 16, 16, 16, __nv_bfloat16, wmma::col_major> ah[4], al[4];
      wmma::fragment<wmma::matrix_b, 16, 16, 16, __nv_bfloat16, wmma::row_major> bh[2], bl[2];
#pragma unroll
      for (int i = 0; i < 4; i++) {
        wmma::load_matrix_sync(ah[i], &sAhi[kk * 16 * ALD + wm * 64 + i * 16], ALD);
        wmma::load_matrix_sync(al[i], &sAlo[kk * 16 * ALD + wm * 64 + i * 16], ALD);
      }
#pragma unroll
      for (int j = 0; j < 2; j++) {
        wmma::load_matrix_sync(bh[j], &sBhi[kk * 16 * ALD + wf * 32 + j * 16], ALD);
        wmma::load_matrix_sync(bl[j], &sBlo[kk * 16 * ALD + wf * 32 + j * 16], ALD);
      }
#pragma unroll
      for (int i = 0; i < 4; i++)
#pragma unroll
        for (int j = 0; j < 2; j++) {
          wmma::mma_sync(acc[i][j], ah[i], bh[j], acc[i][j]);
          wmma::mma_sync(acc[i][j], ah[i], bl[j], acc[i][j]);
          wmma::mma_sync(acc[i][j], al[i], bh[j], acc[i][j]);
        }
    }
  }

  float* pbase = g_part + (size_t)blockIdx.z * M_CL * PF;
#pragma unroll
  for (int i = 0; i < 4; i++)
#pragma unroll
    for (int j = 0; j < 2; j++)
      wmma::store_matrix_sync(
          &pbase[(size_t)(m0 + wm * 64 + i * 16) * PF + f0 + wf * 32 + j * 16],
          acc[i][j], PF, wmma::mem_row_major);
}

// ---------------------------------------------------------------------------
// reduce: g_part[16][256][640] -> g_S[256][640].
// ---------------------------------------------------------------------------
__global__ void __launch_bounds__(256) reduce_kernel() {
  int idx = blockIdx.x * 256 + threadIdx.x;
  float a = 0.0f;
#pragma unroll
  for (int ks = 0; ks < KSPLIT; ks++)
    a += g_part[(size_t)ks * M_CL * PF + idx];
  g_S[idx] = a;
}

// ---------------------------------------------------------------------------
// final: one warp per m.
// ---------------------------------------------------------------------------
__global__ void __launch_bounds__(256) final_kernel(const float* __restrict__ Omega,
                                                    float* __restrict__ out) {
  int t = threadIdx.x, wid = t >> 5, lane = t & 31;
  int m = blockIdx.x * 8 + wid;

  const float* Sm = g_S + (size_t)m * PF;
  const float* Gm = g_gtri + (size_t)m * 528;

  float s_l = Sm[lane];
  float Z   = Sm[560];

  float tr = 0.0f;
#pragma unroll
  for (int i = 0; i < 17; i++) {
    int ft = lane + i * 32;
    if (ft < 528) tr = fmaf(Gm[ft], Sm[32 + ft], tr);
  }

  const float* Om = Omega + (size_t)m * KD * KD + lane * KD;
  float u = 0.0f;
#pragma unroll
  for (int q4 = 0; q4 < 8; q4++) {
    float4 o4 = *reinterpret_cast<const float4*>(Om + 4 * q4);
    u = fmaf(o4.x, __shfl_sync(0xffffffffu, s_l, 4 * q4 + 0), u);
    u = fmaf(o4.y, __shfl_sync(0xffffffffu, s_l, 4 * q4 + 1), u);
    u = fmaf(o4.z, __shfl_sync(0xffffffffu, s_l, 4 * q4 + 2), u);
    u = fmaf(o4.w, __shfl_sync(0xffffffffu, s_l, 4 * q4 + 3), u);
  }
  float usq = u * u;

  float c = 0.0f;
#pragma unroll
  for (int i = 0; i < CNT_BLKS / 32; i++)
    c += g_cnt[(lane * (CNT_BLKS / 32) + i) * M_CL + m];

#pragma unroll
  for (int s = 16; s > 0; s >>= 1) {
    tr  += __shfl_down_sync(0xffffffffu, tr, s);
    usq += __shfl_down_sync(0xffffffffu, usq, s);
    c   += __shfl_down_sync(0xffffffffu, c, s);
  }
  if (lane == 0) {
    float Zs  = fmaxf(Z, 1e-30f);
    float psi = tr / Zs - usq / (Zs * Zs);
    out[m] = (c >= 1.5f) ? psi : 0.0f;
  }
}

// ---------------------------------------------------------------------------
extern "C" void kernel_launch(void* const* d_in, const int* in_sizes, int n_in,
                              void* d_out, int out_size) {
  const float* W            = (const float*)d_in[0];  // (N, M)
  const float* mu_s         = (const float*)d_in[1];  // (N, K)
  const float* omega_child  = (const float*)d_in[2];  // (N, K, K)
  const float* omega_parent = (const float*)d_in[3];  // (M, K, K)
  float* out = (float*)d_out;                         // (M,)

  gsq_kernel<<<M_CL, 256>>>(omega_parent);
  solve_feat_kernel<<<N_AG / 8, 256>>>(omega_child, mu_s);
  cnt_kernel<<<CNT_BLKS, 256>>>(W);
  tgemm_kernel<<<dim3(2, 5, KSPLIT), 256>>>(W);
  reduce_kernel<<<(M_CL * PF) / 256, 256>>>();
  final_kernel<<<M_CL / 8, 256>>>(omega_parent, out);
}

// round 9
// speedup vs baseline: 1.1844x; 1.0630x over previous
#include <cuda_runtime.h>
#include <cuda_bf16.h>
#include <mma.h>
#include <cstdint>

using namespace nvcuda;

#define N_AG 4096
#define M_CL 256
#define KD 32
#define PF 640             /* padded feature count (5*128) */
#define KSPLIT 16
#define CNT_BLKS 128
#define W_EPS 1e-6f

// static scratch (no allocations allowed)
__device__ __align__(16) __nv_bfloat16 g_Whi[(size_t)N_AG * M_CL];  // masked, [n][m]
__device__ __align__(16) __nv_bfloat16 g_Wlo[(size_t)N_AG * M_CL];
__device__ __align__(16) __nv_bfloat16 g_Phi[(size_t)N_AG * PF];    // [n][f]
__device__ __align__(16) __nv_bfloat16 g_Plo[(size_t)N_AG * PF];
__device__ float g_part[(size_t)KSPLIT * M_CL * PF];
__device__ float g_S[(size_t)M_CL * PF];
__device__ float g_gtri[(size_t)M_CL * 528];
__device__ float g_cnt[CNT_BLKS * M_CL];

// ---------------------------------------------------------------------------
// Kernel A: batched 32x32 SPD solve fused with feature build.
// Epilogue emits features directly as bf16 hi/lo (saves fp32 P entirely).
// ---------------------------------------------------------------------------
__global__ void __launch_bounds__(256) solve_feat_kernel(const float* __restrict__ A,
                                                         const float* __restrict__ rhs) {
  __shared__ __align__(16) float prow[8][36];
  int t = threadIdx.x, wid = t >> 5, lane = t & 31;
  int n = blockIdx.x * 8 + wid;
  const float* Ar = A + (size_t)n * (KD * KD) + lane * KD;

  float a[KD];
#pragma unroll
  for (int q = 0; q < 8; q++) {
    float4 v4 = *reinterpret_cast<const float4*>(Ar + 4 * q);
    a[4 * q + 0] = v4.x; a[4 * q + 1] = v4.y;
    a[4 * q + 2] = v4.z; a[4 * q + 3] = v4.w;
  }
  float b = rhs[n * KD + lane];
  float diag = 1.0f;
  float* pr = prow[wid];

#pragma unroll
  for (int j = 0; j < KD; j++) {
    if (lane == j) {
#pragma unroll
      for (int q = 0; q < 8; q++)
        if (4 * q + 3 >= j)
          *reinterpret_cast<float4*>(&pr[4 * q]) =
              make_float4(a[4 * q], a[4 * q + 1], a[4 * q + 2], a[4 * q + 3]);
      pr[32] = b;
      diag = a[j];
    }
    __syncwarp();
    float pd  = pr[j];
    float bp  = pr[32];
    float inv = 1.0f / pd;
    float f   = (lane == j) ? 0.0f : a[j] * inv;
#pragma unroll
    for (int q = 0; q < 8; q++)
      if (4 * q + 3 >= j) {
        float4 pv = *reinterpret_cast<const float4*>(&pr[4 * q]);
        a[4 * q + 0] = fmaf(-f, pv.x, a[4 * q + 0]);
        a[4 * q + 1] = fmaf(-f, pv.y, a[4 * q + 1]);
        a[4 * q + 2] = fmaf(-f, pv.z, a[4 * q + 2]);
        a[4 * q + 3] = fmaf(-f, pv.w, a[4 * q + 3]);
      }
    b = fmaf(-f, bp, b);
    __syncwarp();
  }
  float x = b / diag;

  pr[lane] = x;
  __syncwarp();
  float xv[KD];
#pragma unroll
  for (int q = 0; q < 8; q++) {
    float4 v4 = *reinterpret_cast<const float4*>(&pr[4 * q]);
    xv[4 * q + 0] = v4.x; xv[4 * q + 1] = v4.y;
    xv[4 * q + 2] = v4.z; xv[4 * q + 3] = v4.w;
  }
  __nv_bfloat16* Ph = g_Phi + (size_t)n * PF;
  __nv_bfloat16* Pl = g_Plo + (size_t)n * PF;
  {
    __nv_bfloat16 h = __float2bfloat16(x);
    Ph[lane] = h;
    Pl[lane] = __float2bfloat16(x - __bfloat162float(h));
  }
  int base = KD;
#pragma unroll
  for (int k = 0; k < KD; k++) {
    if (lane >= k) {
      float val = xv[k] * x;
      __nv_bfloat16 h = __float2bfloat16(val);
      Ph[base + lane - k] = h;
      Pl[base + lane - k] = __float2bfloat16(val - __bfloat162float(h));
    }
    base += KD - k;
  }
  const __nv_bfloat16 bz = __float2bfloat16(0.0f);
  if (lane == 0) { Ph[560] = __float2bfloat16(1.0f); Pl[560] = bz; }
  for (int f = 561 + lane; f < PF; f += 32) { Ph[f] = bz; Pl[f] = bz; }
}

// ---------------------------------------------------------------------------
// gsq: per-m packed triangle of G = Omega^2 with symmetry multiplier.
// ---------------------------------------------------------------------------
__global__ void __launch_bounds__(256) gsq_kernel(const float* __restrict__ Omega) {
  __shared__ float sO[KD * KD];
  int m = blockIdx.x, t = threadIdx.x;
  for (int e = t; e < KD * KD; e += 256) sO[e] = Omega[(size_t)m * KD * KD + e];
  __syncthreads();
  for (int ft = t; ft < 528; ft += 256) {
    float disc = 4225.0f - 8.0f * (float)ft;
    int k = (int)((65.0f - sqrtf(disc)) * 0.5f);
    int b0 = k * KD - (k * (k - 1)) / 2;
    if (ft < b0) { k--; b0 = k * KD - (k * (k - 1)) / 2; }
    else if (ft >= b0 + (KD - k)) { k++; b0 = k * KD - (k * (k - 1)) / 2; }
    int l = k + (ft - b0);
    float g = 0.0f;
#pragma unroll
    for (int q = 0; q < KD; q++) g = fmaf(sO[k * KD + q], sO[l * KD + q], g);
    g_gtri[(size_t)m * 528 + ft] = (k == l) ? g : 2.0f * g;
  }
}

// ---------------------------------------------------------------------------
// prepW + cnt (fused): one pass over W -> masked bf16 hi/lo + per-block count.
// Block = 32 n-rows; group rg (4) covers 8 rows for its 4-m quad.
// ---------------------------------------------------------------------------
__global__ void __launch_bounds__(256) prepw_cnt_kernel(const float* __restrict__ W) {
  __shared__ float sc[4][256];
  int t = threadIdx.x;
  int rg = t >> 6, m4 = (t & 63) * 4;
  int nb = blockIdx.x * 32 + rg * 8;
  float4 c = make_float4(0.f, 0.f, 0.f, 0.f);
#pragma unroll
  for (int i = 0; i < 8; i++) {
    int n = nb + i;
    float4 w = *reinterpret_cast<const float4*>(&W[(size_t)n * M_CL + m4]);
    c.x += (w.x >= W_EPS) ? 1.0f : 0.0f;
    c.y += (w.y >= W_EPS) ? 1.0f : 0.0f;
    c.z += (w.z >= W_EPS) ? 1.0f : 0.0f;
    c.w += (w.w >= W_EPS) ? 1.0f : 0.0f;
    w.x = (w.x >= W_EPS) ? w.x : 0.0f;
    w.y = (w.y >= W_EPS) ? w.y : 0.0f;
    w.z = (w.z >= W_EPS) ? w.z : 0.0f;
    w.w = (w.w >= W_EPS) ? w.w : 0.0f;
    __nv_bfloat162 h01, h23, l01, l23;
    h01.x = __float2bfloat16(w.x); h01.y = __float2bfloat16(w.y);
    h23.x = __float2bfloat16(w.z); h23.y = __float2bfloat16(w.w);
    l01.x = __float2bfloat16(w.x - __bfloat162float(h01.x));
    l01.y = __float2bfloat16(w.y - __bfloat162float(h01.y));
    l23.x = __float2bfloat16(w.z - __bfloat162float(h23.x));
    l23.y = __float2bfloat16(w.w - __bfloat162float(h23.y));
    *reinterpret_cast<__nv_bfloat162*>(&g_Whi[(size_t)n * M_CL + m4])     = h01;
    *reinterpret_cast<__nv_bfloat162*>(&g_Whi[(size_t)n * M_CL + m4 + 2]) = h23;
    *reinterpret_cast<__nv_bfloat162*>(&g_Wlo[(size_t)n * M_CL + m4])     = l01;
    *reinterpret_cast<__nv_bfloat162*>(&g_Wlo[(size_t)n * M_CL + m4 + 2]) = l23;
  }
  *reinterpret_cast<float4*>(&sc[rg][m4]) = c;
  __syncthreads();
  if (t < 64) {
    int m = t * 4;
    float4 a0 = *reinterpret_cast<float4*>(&sc[0][m]);
    float4 a1 = *reinterpret_cast<float4*>(&sc[1][m]);
    float4 a2 = *reinterpret_cast<float4*>(&sc[2][m]);
    float4 a3 = *reinterpret_cast<float4*>(&sc[3][m]);
    float4 o = make_float4(a0.x + a1.x + a2.x + a3.x, a0.y + a1.y + a2.y + a3.y,
                           a0.z + a1.z + a2.z + a3.z, a0.w + a1.w + a2.w + a3.w);
    *reinterpret_cast<float4*>(&g_cnt[blockIdx.x * M_CL + m]) = o;
  }
}

// ---------------------------------------------------------------------------
// tgemm: pure-bf16 wmma GEMM (no converts in loop).
// CTA = 128 thr / 4 warps, tile 64m x 128f; warp tile 64m x 32f (acc 4x2).
// grid (4, 5, 16) = 320 CTAs -> 2-3 co-resident CTAs/SM hide sync latency.
// 3 mma passes per frag pair: hi*hi + hi*lo + lo*hi.
// ---------------------------------------------------------------------------
#define ALA 72    /* A smem leading dim (bf16) */
#define ALB 136   /* B smem leading dim (bf16) */

__global__ void __launch_bounds__(128) tgemm_kernel() {
  __shared__ __align__(16) __nv_bfloat16 sAh[32 * ALA], sAl[32 * ALA];
  __shared__ __align__(16) __nv_bfloat16 sBh[32 * ALB], sBl[32 * ALB];

  int t = threadIdx.x, wid = t >> 5;
  int m0 = blockIdx.x * 64;
  int f0 = blockIdx.y * 128;
  int nb = blockIdx.z * (N_AG / KSPLIT);   // 256 n per split
  int row = t >> 2;                        // 0..31
  int cA  = (t & 3) * 16;                  // 16 bf16 per thread (A)
  int cB  = (t & 3) * 32;                  // 32 bf16 per thread (B)

  wmma::fragment<wmma::accumulator, 16, 16, 16, float> acc[4][2];
#pragma unroll
  for (int i = 0; i < 4; i++)
#pragma unroll
    for (int j = 0; j < 2; j++) wmma::fill_fragment(acc[i][j], 0.0f);

  for (int ch = 0; ch < 8; ch++) {
    int n0 = nb + ch * 32;
    __syncthreads();
    {
      const uint4* wh = reinterpret_cast<const uint4*>(
          &g_Whi[(size_t)(n0 + row) * M_CL + m0 + cA]);
      const uint4* wl = reinterpret_cast<const uint4*>(
          &g_Wlo[(size_t)(n0 + row) * M_CL + m0 + cA]);
      *reinterpret_cast<uint4*>(&sAh[row * ALA + cA])     = wh[0];
      *reinterpret_cast<uint4*>(&sAh[row * ALA + cA + 8]) = wh[1];
      *reinterpret_cast<uint4*>(&sAl[row * ALA + cA])     = wl[0];
      *reinterpret_cast<uint4*>(&sAl[row * ALA + cA + 8]) = wl[1];
      const uint4* ph = reinterpret_cast<const uint4*>(
          &g_Phi[(size_t)(n0 + row) * PF + f0 + cB]);
      const uint4* pl = reinterpret_cast<const uint4*>(
          &g_Plo[(size_t)(n0 + row) * PF + f0 + cB]);
#pragma unroll
      for (int u = 0; u < 4; u++) {
        *reinterpret_cast<uint4*>(&sBh[row * ALB + cB + u * 8]) = ph[u];
        *reinterpret_cast<uint4*>(&sBl[row * ALB + cB + u * 8]) = pl[u];
      }
    }
    __syncthreads();
#pragma unroll
    for (int kk = 0; kk < 2; kk++) {
      wmma::fragment<wmma::matrix_a, 16, 16, 16, __nv_bfloat16, wmma::col_major> ah[4], al[4];
      wmma::fragment<wmma::matrix_b, 16, 16, 16, __nv_bfloat16, wmma::row_major> bh[2], bl[2];
#pragma unroll
      for (int i = 0; i < 4; i++) {
        wmma::load_matrix_sync(ah[i], &sAh[kk * 16 * ALA + i * 16], ALA);
        wmma::load_matrix_sync(al[i], &sAl[kk * 16 * ALA + i * 16], ALA);
      }
#pragma unroll
      for (int j = 0; j < 2; j++) {
        wmma::load_matrix_sync(bh[j], &sBh[kk * 16 * ALB + wid * 32 + j * 16], ALB);
        wmma::load_matrix_sync(bl[j], &sBl[kk * 16 * ALB + wid * 32 + j * 16], ALB);
      }
#pragma unroll
      for (int i = 0; i < 4; i++)
#pragma unroll
        for (int j = 0; j < 2; j++) {
          wmma::mma_sync(acc[i][j], ah[i], bh[j], acc[i][j]);
          wmma::mma_sync(acc[i][j], ah[i], bl[j], acc[i][j]);
          wmma::mma_sync(acc[i][j], al[i], bh[j], acc[i][j]);
        }
    }
  }

  float* pbase = g_part + (size_t)blockIdx.z * M_CL * PF;
#pragma unroll
  for (int i = 0; i < 4; i++)
#pragma unroll
    for (int j = 0; j < 2; j++)
      wmma::store_matrix_sync(
          &pbase[(size_t)(m0 + i * 16) * PF + f0 + wid * 32 + j * 16],
          acc[i][j], PF, wmma::mem_row_major);
}

// ---------------------------------------------------------------------------
// reduce: g_part[16][256][640] -> g_S[256][640].
// ---------------------------------------------------------------------------
__global__ void __launch_bounds__(256) reduce_kernel() {
  int idx = blockIdx.x * 256 + threadIdx.x;
  float a = 0.0f;
#pragma unroll
  for (int ks = 0; ks < KSPLIT; ks++)
    a += g_part[(size_t)ks * M_CL * PF + idx];
  g_S[idx] = a;
}

// ---------------------------------------------------------------------------
// final: one warp per m.
// ---------------------------------------------------------------------------
__global__ void __launch_bounds__(256) final_kernel(const float* __restrict__ Omega,
                                                    float* __restrict__ out) {
  int t = threadIdx.x, wid = t >> 5, lane = t & 31;
  int m = blockIdx.x * 8 + wid;

  const float* Sm = g_S + (size_t)m * PF;
  const float* Gm = g_gtri + (size_t)m * 528;

  float s_l = Sm[lane];
  float Z   = Sm[560];

  float tr = 0.0f;
#pragma unroll
  for (int i = 0; i < 17; i++) {
    int ft = lane + i * 32;
    if (ft < 528) tr = fmaf(Gm[ft], Sm[32 + ft], tr);
  }

  const float* Om = Omega + (size_t)m * KD * KD + lane * KD;
  float u = 0.0f;
#pragma unroll
  for (int q4 = 0; q4 < 8; q4++) {
    float4 o4 = *reinterpret_cast<const float4*>(Om + 4 * q4);
    u = fmaf(o4.x, __shfl_sync(0xffffffffu, s_l, 4 * q4 + 0), u);
    u = fmaf(o4.y, __shfl_sync(0xffffffffu, s_l, 4 * q4 + 1), u);
    u = fmaf(o4.z, __shfl_sync(0xffffffffu, s_l, 4 * q4 + 2), u);
    u = fmaf(o4.w, __shfl_sync(0xffffffffu, s_l, 4 * q4 + 3), u);
  }
  float usq = u * u;

  float c = 0.0f;
#pragma unroll
  for (int i = 0; i < CNT_BLKS / 32; i++)
    c += g_cnt[(lane * (CNT_BLKS / 32) + i) * M_CL + m];

#pragma unroll
  for (int s = 16; s > 0; s >>= 1) {
    tr  += __shfl_down_sync(0xffffffffu, tr, s);
    usq += __shfl_down_sync(0xffffffffu, usq, s);
    c   += __shfl_down_sync(0xffffffffu, c, s);
  }
  if (lane == 0) {
    float Zs  = fmaxf(Z, 1e-30f);
    float psi = tr / Zs - usq / (Zs * Zs);
    out[m] = (c >= 1.5f) ? psi : 0.0f;
  }
}

// ---------------------------------------------------------------------------
extern "C" void kernel_launch(void* const* d_in, const int* in_sizes, int n_in,
                              void* d_out, int out_size) {
  const float* W            = (const float*)d_in[0];  // (N, M)
  const float* mu_s         = (const float*)d_in[1];  // (N, K)
  const float* omega_child  = (const float*)d_in[2];  // (N, K, K)
  const float* omega_parent = (const float*)d_in[3];  // (M, K, K)
  float* out = (float*)d_out;                         // (M,)

  gsq_kernel<<<M_CL, 256>>>(omega_parent);
  solve_feat_kernel<<<N_AG / 8, 256>>>(omega_child, mu_s);
  prepw_cnt_kernel<<<CNT_BLKS, 256>>>(W);
  tgemm_kernel<<<dim3(M_CL / 64, PF / 128, KSPLIT), 128>>>();
  reduce_kernel<<<(M_CL * PF) / 256, 256>>>();
  final_kernel<<<M_CL / 8, 256>>>(omega_parent, out);
}